// round 3
// baseline (speedup 1.0000x reference)
#include <cuda_runtime.h>

#define FULLMASK 0xffffffffu
#define IH 256
#define IW 192

typedef unsigned long long u64;

// Gaussian taps for kernel_size=11, sigma=10/6, normalized. Indexed by |d|.
static __device__ __forceinline__ float wt(int k) {
    const float t[6] = {0.23955940f, 0.20009682f, 0.11660614f,
                        0.04740849f, 0.01344761f, 0.00266126f};
    return t[k];
}

static __device__ __forceinline__ u64 pk(float lo, float hi) {
    u64 r; asm("mov.b64 %0, {%1, %2};" : "=l"(r) : "f"(lo), "f"(hi)); return r;
}
static __device__ __forceinline__ void upk(u64 v, float& lo, float& hi) {
    asm("mov.b64 {%0, %1}, %2;" : "=f"(lo), "=f"(hi) : "l"(v));
}
static __device__ __forceinline__ u64 f2mul(u64 a, u64 b) {
    u64 d; asm("mul.rn.f32x2 %0, %1, %2;" : "=l"(d) : "l"(a), "l"(b)); return d;
}
static __device__ __forceinline__ u64 f2fma(u64 a, u64 b, u64 c) {
    u64 d; asm("fma.rn.f32x2 %0, %1, %2, %3;" : "=l"(d) : "l"(a), "l"(b), "l"(c)); return d;
}

// One CTA (128 threads = 4 warps) per (b,k) image.
// Warp w produces blurred rows [w*64, w*64+64): lane owns 6 columns,
// hblur via shuffled halos + packed f32x2 FMAs, vblur via 11-slot packed
// rotating register accumulator.
#define ROWS_PER_WARP 64
#define NITER (ROWS_PER_WARP + 10)   // 74

__global__ __launch_bounds__(128, 4)
void dark_decode_kernel(const float* __restrict__ hm,
                        float* __restrict__ out, int n_img)
{
    const int img  = blockIdx.x;
    const int warp = threadIdx.x >> 5;
    const int lane = threadIdx.x & 31;
    const float* __restrict__ ip = hm + (long long)img * (IH * IW);
    const int base = warp * ROWS_PER_WARP;   // output rows [base, base+64)
    const int col0 = lane * 6;

    // packed weights (both halves equal), index = |d|
    u64 w2[6];
#pragma unroll
    for (int k = 0; k < 6; ++k) w2[k] = pk(wt(k), wt(k));

    // packed accumulators: 11 slots x 3 column-pairs
    u64 acc[11][3];
#pragma unroll
    for (int k = 0; k < 11; ++k)
#pragma unroll
        for (int c = 0; c < 3; ++c) acc[k][c] = 0ull;

    // prologue: load row (base-5) if it exists
    float2 cur0, cur1, cur2;
    {
        const int r0 = base - 5;
        if (r0 >= 0 && r0 < IH) {
            const float* rp = ip + r0 * IW + col0;
            cur0 = *(const float2*)(rp);
            cur1 = *(const float2*)(rp + 2);
            cur2 = *(const float2*)(rp + 4);
        } else {
            cur0 = make_float2(0.f, 0.f); cur1 = cur0; cur2 = cur0;
        }
    }

    float bestv   = -3.4e38f;
    int   bestlin = 0;

    // i = 0..NITER-1 ; row r = base-5+i ; output row ro = base+i-10 at i>=10
    for (int ib = 0; ib < (NITER + 10) / 11; ++ib) {
#pragma unroll
        for (int u = 0; u < 11; ++u) {
            const int i = ib * 11 + u;
            if (i < NITER) {
                const int r = base - 5 + i;

                // prefetch next row
                float2 nxt0, nxt1, nxt2;
                {
                    const int rn = r + 1;
                    if ((i + 1 < NITER) && rn >= 0 && rn < IH) {
                        const float* rp = ip + rn * IW + col0;
                        nxt0 = *(const float2*)(rp);
                        nxt1 = *(const float2*)(rp + 2);
                        nxt2 = *(const float2*)(rp + 4);
                    } else {
                        nxt0 = make_float2(0.f, 0.f); nxt1 = nxt0; nxt2 = nxt0;
                    }
                }

                if (r >= 0 && r < IH) {
                    // extended segment e[0..15] = cols col0-5 .. col0+10 (zero-padded)
                    float e[16];
                    e[5] = cur0.x; e[6] = cur0.y; e[7] = cur1.x;
                    e[8] = cur1.y; e[9] = cur2.x; e[10] = cur2.y;
                    e[0]  = __shfl_up_sync(FULLMASK, e[6],  1);
                    e[1]  = __shfl_up_sync(FULLMASK, e[7],  1);
                    e[2]  = __shfl_up_sync(FULLMASK, e[8],  1);
                    e[3]  = __shfl_up_sync(FULLMASK, e[9],  1);
                    e[4]  = __shfl_up_sync(FULLMASK, e[10], 1);
                    e[11] = __shfl_down_sync(FULLMASK, e[5], 1);
                    e[12] = __shfl_down_sync(FULLMASK, e[6], 1);
                    e[13] = __shfl_down_sync(FULLMASK, e[7], 1);
                    e[14] = __shfl_down_sync(FULLMASK, e[8], 1);
                    e[15] = __shfl_down_sync(FULLMASK, e[9], 1);
                    if (lane == 0)  { e[0]=0.f; e[1]=0.f; e[2]=0.f; e[3]=0.f; e[4]=0.f; }
                    if (lane == 31) { e[11]=0.f; e[12]=0.f; e[13]=0.f; e[14]=0.f; e[15]=0.f; }

                    // all adjacent pairs P[o] = (e[o], e[o+1]), o = 0..14
                    u64 P[15];
#pragma unroll
                    for (int o = 0; o < 15; ++o) P[o] = pk(e[o], e[o + 1]);

                    // horizontal blur, packed: h2[j] = (h[2j], h[2j+1])
                    u64 h2[3];
#pragma unroll
                    for (int j = 0; j < 3; ++j) {
                        u64 sa = f2mul(P[2*j + 0], w2[5]);      // d=0
                        sa = f2fma(P[2*j + 2],  w2[3], sa);     // d=2
                        sa = f2fma(P[2*j + 4],  w2[1], sa);     // d=4
                        sa = f2fma(P[2*j + 6],  w2[1], sa);     // d=6
                        sa = f2fma(P[2*j + 8],  w2[3], sa);     // d=8
                        sa = f2fma(P[2*j + 10], w2[5], sa);     // d=10
                        u64 sb = f2mul(P[2*j + 1], w2[4]);      // d=1
                        sb = f2fma(P[2*j + 3],  w2[2], sb);     // d=3
                        sb = f2fma(P[2*j + 5],  w2[0], sb);     // d=5
                        sb = f2fma(P[2*j + 7],  w2[2], sb);     // d=7
                        sb = f2fma(P[2*j + 9],  w2[4], sb);     // d=9
                        u64 s;
                        asm("add.rn.f32x2 %0, %1, %2;" : "=l"(s) : "l"(sa), "l"(sb));
                        h2[j] = s;
                    }

                    // vertical blur accumulation: slot (u+k)%11 is static
#pragma unroll
                    for (int k = 0; k < 11; ++k) {
                        const u64 wv = w2[k <= 5 ? 5 - k : k - 5];
                        const int slot = (u + k) % 11;
                        acc[slot][0] = f2fma(h2[0], wv, acc[slot][0]);
                        acc[slot][1] = f2fma(h2[1], wv, acc[slot][1]);
                        acc[slot][2] = f2fma(h2[2], wv, acc[slot][2]);
                    }
                }

                // emit completed output row ro = base+i-10 (slot u), recycle slot
                if (i >= 10) {
                    float a0, a1, a2, a3, a4, a5;
                    upk(acc[u][0], a0, a1);
                    upk(acc[u][1], a2, a3);
                    upk(acc[u][2], a4, a5);
                    const float m01 = fmaxf(a0, a1);
                    const float m23 = fmaxf(a2, a3);
                    const float m45 = fmaxf(a4, a5);
                    const float rowmax = fmaxf(fmaxf(m01, m23), m45);
                    if (rowmax > bestv) {        // rare
                        bestv = rowmax;
                        int c = 5;
                        if (a4 == rowmax) c = 4;
                        if (a3 == rowmax) c = 3;
                        if (a2 == rowmax) c = 2;
                        if (a1 == rowmax) c = 1;
                        if (a0 == rowmax) c = 0;
                        bestlin = (base + i - 10) * IW + col0 + c;
                    }
                }
                acc[u][0] = 0ull; acc[u][1] = 0ull; acc[u][2] = 0ull;

                cur0 = nxt0; cur1 = nxt1; cur2 = nxt2;
            }
        }
    }

    // intra-warp argmax reduce (larger value wins; tie -> smaller linear index)
#pragma unroll
    for (int off = 16; off >= 1; off >>= 1) {
        const float ov = __shfl_xor_sync(FULLMASK, bestv, off);
        const int   oi = __shfl_xor_sync(FULLMASK, bestlin, off);
        if (ov > bestv || (ov == bestv && oi < bestlin)) { bestv = ov; bestlin = oi; }
    }

    __shared__ float s_v[4];
    __shared__ int   s_i[4];
    if (lane == 0) { s_v[warp] = bestv; s_i[warp] = bestlin; }
    __syncthreads();
    if (warp != 0) return;

    float fv = s_v[0]; int fl = s_i[0];
#pragma unroll
    for (int w = 1; w < 4; ++w) {
        const float vw = s_v[w]; const int iw = s_i[w];
        if (vw > fv || (vw == fv && iw < fl)) { fv = vw; fl = iw; }
    }
    const int py = fl / IW;
    const int px = fl - py * IW;

    float offx = 0.f, offy = 0.f;
    const bool bok = (px >= 1) && (px < IW - 1) && (py >= 1) && (py < IH - 1);
    if (bok) {
        // 39 hblur values: flat j in [0,39), rr = py-6 + j/3, cc = px-1 + j%3
        float h0 = 0.f, h1 = 0.f;
        {
            int j = lane;
            int rr = py - 6 + j / 3;
            int cc = px - 1 + (j - (j / 3) * 3);
            if (rr >= 0 && rr < IH) {
                const float* rp = ip + rr * IW;
                float s = 0.f;
#pragma unroll
                for (int d = -5; d <= 5; ++d) {
                    const int c = cc + d;
                    float v = 0.f;
                    if ((unsigned)c < (unsigned)IW) v = rp[c];
                    s += v * wt(d < 0 ? -d : d);
                }
                h0 = s;
            }
            j = lane + 32;
            if (j < 39) {
                rr = py - 6 + j / 3;
                cc = px - 1 + (j - (j / 3) * 3);
                if (rr >= 0 && rr < IH) {
                    const float* rp = ip + rr * IW;
                    float s = 0.f;
#pragma unroll
                    for (int d = -5; d <= 5; ++d) {
                        const int c = cc + d;
                        float v = 0.f;
                        if ((unsigned)c < (unsigned)IW) v = rp[c];
                        s += v * wt(d < 0 ? -d : d);
                    }
                    h1 = s;
                }
            }
        }
        // lanes 0..8: vertical blur -> patch entry p(a,b), a=lane/3, b=lane%3
        const int a = lane / 3;
        const int b = lane - a * 3;
        float p = 0.f;
#pragma unroll
        for (int t = 0; t < 11; ++t) {
            const int j = (a + t) * 3 + b;
            const float va = __shfl_sync(FULLMASK, h0, j & 31);
            const float vb = __shfl_sync(FULLMASK, h1, j & 31);
            const float hv = (j < 32) ? va : vb;
            p += hv * wt(t <= 5 ? 5 - t : t - 5);
        }
        const float p00 = __shfl_sync(FULLMASK, p, 0);
        const float p01 = __shfl_sync(FULLMASK, p, 1);
        const float p02 = __shfl_sync(FULLMASK, p, 2);
        const float p10 = __shfl_sync(FULLMASK, p, 3);
        const float p11 = __shfl_sync(FULLMASK, p, 4);
        const float p12 = __shfl_sync(FULLMASK, p, 5);
        const float p20 = __shfl_sync(FULLMASK, p, 6);
        const float p21 = __shfl_sync(FULLMASK, p, 7);
        const float p22 = __shfl_sync(FULLMASK, p, 8);

        const float dx  = (p12 - p10) * 0.5f;
        const float dy  = (p21 - p01) * 0.5f;
        const float dxx = p12 - 2.f * p11 + p10;
        const float dyy = p21 - 2.f * p11 + p01;
        const float dxy = (p22 - p20 - p02 + p00) * 0.25f;
        const float det = dxx * dyy - dxy * dxy;
        if (fabsf(det) >= 1e-6f && dxx < 0.f) {
            const float ox = -(dyy * dx - dxy * dy) / det;
            const float oy = -(dxx * dy - dxy * dx) / det;
            offx = fminf(fmaxf(ox, -0.5f), 0.5f);
            offy = fminf(fmaxf(oy, -0.5f), 0.5f);
        }
    }

    if (lane == 0) {
        const float xo = fminf(fmaxf((float)px + offx, 0.f), (float)(IW - 1));
        const float yo = fminf(fmaxf((float)py + offy, 0.f), (float)(IH - 1));
        out[2 * img + 0] = xo;                       // coords[...,0] = x
        out[2 * img + 1] = yo;                       // coords[...,1] = y
        out[(long long)2 * n_img + img] = fv;        // max_vals
    }
}

extern "C" void kernel_launch(void* const* d_in, const int* in_sizes, int n_in,
                              void* d_out, int out_size)
{
    const float* hm = (const float*)d_in[0];
    // d_in[1] is kernel_size (always 11 in this problem; taps are baked in)
    const int n_img = in_sizes[0] / (IH * IW);
    dark_decode_kernel<<<n_img, 128>>>(hm, (float*)d_out, n_img);
}

// round 4
// speedup vs baseline: 1.1759x; 1.1759x over previous
#include <cuda_runtime.h>

#define FULLMASK 0xffffffffu
#define IH 256
#define IW 192

typedef unsigned long long u64;

// Gaussian taps for kernel_size=11, sigma=10/6, normalized. Indexed by |d|.
static __device__ __forceinline__ float wt(int k) {
    const float t[6] = {0.23955940f, 0.20009682f, 0.11660614f,
                        0.04740849f, 0.01344761f, 0.00266126f};
    return t[k];
}

static __device__ __forceinline__ u64 pk(float lo, float hi) {
    u64 r; asm("mov.b64 %0, {%1, %2};" : "=l"(r) : "f"(lo), "f"(hi)); return r;
}
static __device__ __forceinline__ void upk(u64 v, float& lo, float& hi) {
    asm("mov.b64 {%0, %1}, %2;" : "=f"(lo), "=f"(hi) : "l"(v));
}
static __device__ __forceinline__ u64 f2mul(u64 a, u64 b) {
    u64 d; asm("mul.rn.f32x2 %0, %1, %2;" : "=l"(d) : "l"(a), "l"(b)); return d;
}
static __device__ __forceinline__ u64 f2fma(u64 a, u64 b, u64 c) {
    u64 d; asm("fma.rn.f32x2 %0, %1, %2, %3;" : "=l"(d) : "l"(a), "l"(b), "l"(c)); return d;
}
static __device__ __forceinline__ u64 f2add(u64 a, u64 b) {
    u64 d; asm("add.rn.f32x2 %0, %1, %2;" : "=l"(d) : "l"(a), "l"(b)); return d;
}

// shuffle own[6] -> lo[5] (cols -5..-1) and hi[5] (cols +6..+10), zero-padded
// at warp (=image) edges.
static __device__ __forceinline__ void mk_halo(const float* own, float* lo,
                                               float* hi, int lane) {
    lo[0] = __shfl_up_sync(FULLMASK, own[1], 1);
    lo[1] = __shfl_up_sync(FULLMASK, own[2], 1);
    lo[2] = __shfl_up_sync(FULLMASK, own[3], 1);
    lo[3] = __shfl_up_sync(FULLMASK, own[4], 1);
    lo[4] = __shfl_up_sync(FULLMASK, own[5], 1);
    hi[0] = __shfl_down_sync(FULLMASK, own[0], 1);
    hi[1] = __shfl_down_sync(FULLMASK, own[1], 1);
    hi[2] = __shfl_down_sync(FULLMASK, own[2], 1);
    hi[3] = __shfl_down_sync(FULLMASK, own[3], 1);
    hi[4] = __shfl_down_sync(FULLMASK, own[4], 1);
    if (lane == 0)  { lo[0]=0.f; lo[1]=0.f; lo[2]=0.f; lo[3]=0.f; lo[4]=0.f; }
    if (lane == 31) { hi[0]=0.f; hi[1]=0.f; hi[2]=0.f; hi[3]=0.f; hi[4]=0.f; }
}

#define ROWS_PER_WARP 128
#define NITER (ROWS_PER_WARP + 10)   // 138

// One CTA (64 threads = 2 warps) per (b,k) image.
// Warp w produces blurred rows [w*128, w*128+128): lane owns 6 columns.
// 3-stage software pipeline: load row i+2 / shuffle row i+1 / blur row i.
__global__ __launch_bounds__(64, 8)
void dark_decode_kernel(const float* __restrict__ hm,
                        float* __restrict__ out, int n_img)
{
    const int img  = blockIdx.x;
    const int warp = threadIdx.x >> 5;
    const int lane = threadIdx.x & 31;
    const float* __restrict__ ip = hm + (long long)img * (IH * IW);
    const int base = warp * ROWS_PER_WARP;
    const int col0 = lane * 6;

    u64 w2[6];
#pragma unroll
    for (int k = 0; k < 6; ++k) w2[k] = pk(wt(k), wt(k));

    u64 acc[11][3];
#pragma unroll
    for (int k = 0; k < 11; ++k)
#pragma unroll
        for (int c = 0; c < 3; ++c) acc[k][c] = 0ull;

    // pipeline state:
    float eo[6];            // own cols of row r_i (shuffled era)
    float hl[5], hh[5];     // halos of row r_i
    float ld[6];            // raw row r_{i+1}

    // prologue: row r0 = base-5 -> eo/halos ; row r1 -> ld
    {
        const int r0 = base - 5;
        if (r0 >= 0 && r0 < IH) {
            const float* rp = ip + r0 * IW + col0;
            float2 a = *(const float2*)rp, b = *(const float2*)(rp+2),
                   c = *(const float2*)(rp+4);
            eo[0]=a.x; eo[1]=a.y; eo[2]=b.x; eo[3]=b.y; eo[4]=c.x; eo[5]=c.y;
        } else {
#pragma unroll
            for (int c = 0; c < 6; ++c) eo[c] = 0.f;
        }
        mk_halo(eo, hl, hh, lane);
        const int r1 = r0 + 1;
        if (r1 >= 0 && r1 < IH) {
            const float* rp = ip + r1 * IW + col0;
            float2 a = *(const float2*)rp, b = *(const float2*)(rp+2),
                   c = *(const float2*)(rp+4);
            ld[0]=a.x; ld[1]=a.y; ld[2]=b.x; ld[3]=b.y; ld[4]=c.x; ld[5]=c.y;
        } else {
#pragma unroll
            for (int c = 0; c < 6; ++c) ld[c] = 0.f;
        }
    }

    float bestv   = -3.4e38f;
    int   bestlin = 0;

    for (int ib = 0; ib < (NITER + 10) / 11; ++ib) {
#pragma unroll
        for (int u = 0; u < 11; ++u) {
            const int i = ib * 11 + u;
            if (i < NITER) {
                const int r = base - 5 + i;

                // stage 1: load row r+2 (for iter i+2)
                float ldn[6];
                {
                    const int rn = r + 2;
                    if ((i + 2 < NITER) && rn >= 0 && rn < IH) {
                        const float* rp = ip + rn * IW + col0;
                        float2 a = *(const float2*)rp, b = *(const float2*)(rp+2),
                               c = *(const float2*)(rp+4);
                        ldn[0]=a.x; ldn[1]=a.y; ldn[2]=b.x;
                        ldn[3]=b.y; ldn[4]=c.x; ldn[5]=c.y;
                    } else {
#pragma unroll
                        for (int c = 0; c < 6; ++c) ldn[c] = 0.f;
                    }
                }

                float nhl[5], nhh[5];
                if (r >= 0 && r < IH) {
                    // build adjacent pairs from current row's extended segment
                    // E[t]: t<5 -> hl[t]; 5..10 -> eo[t-5]; 11..15 -> hh[t-11]
                    u64 P[15];
                    P[0]  = pk(hl[0], hl[1]);
                    P[1]  = pk(hl[1], hl[2]);
                    P[2]  = pk(hl[2], hl[3]);
                    P[3]  = pk(hl[3], hl[4]);
                    P[4]  = pk(hl[4], eo[0]);
                    P[5]  = pk(eo[0], eo[1]);
                    P[6]  = pk(eo[1], eo[2]);
                    P[7]  = pk(eo[2], eo[3]);
                    P[8]  = pk(eo[3], eo[4]);
                    P[9]  = pk(eo[4], eo[5]);
                    P[10] = pk(eo[5], hh[0]);
                    P[11] = pk(hh[0], hh[1]);
                    P[12] = pk(hh[1], hh[2]);
                    P[13] = pk(hh[2], hh[3]);
                    P[14] = pk(hh[3], hh[4]);

                    // stage 2 (early): shuffle row r+1 -> next halos.
                    // Issued here so the 26-cyc SHFL latency is covered by the
                    // hblur/vblur FMA stream below.
                    mk_halo(ld, nhl, nhh, lane);

                    // stage 3: horizontal blur (packed, even/odd split chains)
                    u64 h2[3];
#pragma unroll
                    for (int j = 0; j < 3; ++j) {
                        u64 sa = f2mul(P[2*j + 0], w2[5]);
                        sa = f2fma(P[2*j + 2],  w2[3], sa);
                        sa = f2fma(P[2*j + 4],  w2[1], sa);
                        sa = f2fma(P[2*j + 6],  w2[1], sa);
                        sa = f2fma(P[2*j + 8],  w2[3], sa);
                        sa = f2fma(P[2*j + 10], w2[5], sa);
                        u64 sb = f2mul(P[2*j + 1], w2[4]);
                        sb = f2fma(P[2*j + 3],  w2[2], sb);
                        sb = f2fma(P[2*j + 5],  w2[0], sb);
                        sb = f2fma(P[2*j + 7],  w2[2], sb);
                        sb = f2fma(P[2*j + 9],  w2[4], sb);
                        h2[j] = f2add(sa, sb);
                    }

                    // vertical blur: k=10 initializes the recycled slot
                    // (overwrite), k=0..9 accumulate.
#pragma unroll
                    for (int k = 0; k < 10; ++k) {
                        const u64 wv = w2[k <= 5 ? 5 - k : k - 5];
                        const int slot = (u + k) % 11;
                        acc[slot][0] = f2fma(h2[0], wv, acc[slot][0]);
                        acc[slot][1] = f2fma(h2[1], wv, acc[slot][1]);
                        acc[slot][2] = f2fma(h2[2], wv, acc[slot][2]);
                    }
                    {
                        const int slot = (u + 10) % 11;
                        acc[slot][0] = f2mul(h2[0], w2[5]);
                        acc[slot][1] = f2mul(h2[1], w2[5]);
                        acc[slot][2] = f2mul(h2[2], w2[5]);
                    }
                } else {
                    mk_halo(ld, nhl, nhh, lane);
                    const int slot = (u + 10) % 11;
                    acc[slot][0] = 0ull; acc[slot][1] = 0ull; acc[slot][2] = 0ull;
                }

                // emit completed output row ro = base+i-10 (slot u)
                if (i >= 10) {
                    float a0, a1, a2, a3, a4, a5;
                    upk(acc[u][0], a0, a1);
                    upk(acc[u][1], a2, a3);
                    upk(acc[u][2], a4, a5);
                    const float m01 = fmaxf(a0, a1);
                    const float m23 = fmaxf(a2, a3);
                    const float m45 = fmaxf(a4, a5);
                    const float rowmax = fmaxf(fmaxf(m01, m23), m45);
                    if (rowmax > bestv) {        // rare
                        bestv = rowmax;
                        int c = 5;
                        if (a4 == rowmax) c = 4;
                        if (a3 == rowmax) c = 3;
                        if (a2 == rowmax) c = 2;
                        if (a1 == rowmax) c = 1;
                        if (a0 == rowmax) c = 0;
                        bestlin = (base + i - 10) * IW + col0 + c;
                    }
                }

                // rotate pipeline registers (renamed away by unroll)
#pragma unroll
                for (int c = 0; c < 6; ++c) eo[c] = ld[c];
#pragma unroll
                for (int c = 0; c < 5; ++c) { hl[c] = nhl[c]; hh[c] = nhh[c]; }
#pragma unroll
                for (int c = 0; c < 6; ++c) ld[c] = ldn[c];
            }
        }
    }

    // intra-warp argmax reduce (larger value wins; tie -> smaller linear index)
#pragma unroll
    for (int off = 16; off >= 1; off >>= 1) {
        const float ov = __shfl_xor_sync(FULLMASK, bestv, off);
        const int   oi = __shfl_xor_sync(FULLMASK, bestlin, off);
        if (ov > bestv || (ov == bestv && oi < bestlin)) { bestv = ov; bestlin = oi; }
    }

    __shared__ float s_v[2];
    __shared__ int   s_i[2];
    if (lane == 0) { s_v[warp] = bestv; s_i[warp] = bestlin; }
    __syncthreads();
    if (warp != 0) return;

    float fv; int fl;
    {
        const float v0 = s_v[0], v1 = s_v[1];
        const int   i0 = s_i[0], i1 = s_i[1];
        if (v1 > v0 || (v1 == v0 && i1 < i0)) { fv = v1; fl = i1; }
        else                                  { fv = v0; fl = i0; }
    }
    const int py = fl / IW;
    const int px = fl - py * IW;

    float offx = 0.f, offy = 0.f;
    const bool bok = (px >= 1) && (px < IW - 1) && (py >= 1) && (py < IH - 1);
    if (bok) {
        // 39 hblur values: flat j in [0,39), rr = py-6 + j/3, cc = px-1 + j%3
        float h0 = 0.f, h1 = 0.f;
        {
            int j = lane;
            int rr = py - 6 + j / 3;
            int cc = px - 1 + (j - (j / 3) * 3);
            if (rr >= 0 && rr < IH) {
                const float* rp = ip + rr * IW;
                float s = 0.f;
#pragma unroll
                for (int d = -5; d <= 5; ++d) {
                    const int c = cc + d;
                    float v = 0.f;
                    if ((unsigned)c < (unsigned)IW) v = rp[c];
                    s += v * wt(d < 0 ? -d : d);
                }
                h0 = s;
            }
            j = lane + 32;
            if (j < 39) {
                rr = py - 6 + j / 3;
                cc = px - 1 + (j - (j / 3) * 3);
                if (rr >= 0 && rr < IH) {
                    const float* rp = ip + rr * IW;
                    float s = 0.f;
#pragma unroll
                    for (int d = -5; d <= 5; ++d) {
                        const int c = cc + d;
                        float v = 0.f;
                        if ((unsigned)c < (unsigned)IW) v = rp[c];
                        s += v * wt(d < 0 ? -d : d);
                    }
                    h1 = s;
                }
            }
        }
        // lanes 0..8: vertical blur -> patch entry p(a,b), a=lane/3, b=lane%3
        const int a = lane / 3;
        const int b = lane - a * 3;
        float p = 0.f;
#pragma unroll
        for (int t = 0; t < 11; ++t) {
            const int j = (a + t) * 3 + b;
            const float va = __shfl_sync(FULLMASK, h0, j & 31);
            const float vb = __shfl_sync(FULLMASK, h1, j & 31);
            const float hv = (j < 32) ? va : vb;
            p += hv * wt(t <= 5 ? 5 - t : t - 5);
        }
        const float p00 = __shfl_sync(FULLMASK, p, 0);
        const float p01 = __shfl_sync(FULLMASK, p, 1);
        const float p02 = __shfl_sync(FULLMASK, p, 2);
        const float p10 = __shfl_sync(FULLMASK, p, 3);
        const float p11 = __shfl_sync(FULLMASK, p, 4);
        const float p12 = __shfl_sync(FULLMASK, p, 5);
        const float p20 = __shfl_sync(FULLMASK, p, 6);
        const float p21 = __shfl_sync(FULLMASK, p, 7);
        const float p22 = __shfl_sync(FULLMASK, p, 8);

        const float dx  = (p12 - p10) * 0.5f;
        const float dy  = (p21 - p01) * 0.5f;
        const float dxx = p12 - 2.f * p11 + p10;
        const float dyy = p21 - 2.f * p11 + p01;
        const float dxy = (p22 - p20 - p02 + p00) * 0.25f;
        const float det = dxx * dyy - dxy * dxy;
        if (fabsf(det) >= 1e-6f && dxx < 0.f) {
            const float ox = -(dyy * dx - dxy * dy) / det;
            const float oy = -(dxx * dy - dxy * dx) / det;
            offx = fminf(fmaxf(ox, -0.5f), 0.5f);
            offy = fminf(fmaxf(oy, -0.5f), 0.5f);
        }
    }

    if (lane == 0) {
        const float xo = fminf(fmaxf((float)px + offx, 0.f), (float)(IW - 1));
        const float yo = fminf(fmaxf((float)py + offy, 0.f), (float)(IH - 1));
        out[2 * img + 0] = xo;                       // coords[...,0] = x
        out[2 * img + 1] = yo;                       // coords[...,1] = y
        out[(long long)2 * n_img + img] = fv;        // max_vals
    }
}

extern "C" void kernel_launch(void* const* d_in, const int* in_sizes, int n_in,
                              void* d_out, int out_size)
{
    const float* hm = (const float*)d_in[0];
    // d_in[1] is kernel_size (always 11 in this problem; taps are baked in)
    const int n_img = in_sizes[0] / (IH * IW);
    dark_decode_kernel<<<n_img, 64>>>(hm, (float*)d_out, n_img);
}

// round 5
// speedup vs baseline: 1.3161x; 1.1192x over previous
#include <cuda_runtime.h>

#define FULLMASK 0xffffffffu
#define IH 256
#define IW 192

typedef unsigned long long u64;

// Gaussian taps for kernel_size=11, sigma=10/6, normalized. Indexed by |d|.
static __device__ __forceinline__ float wt(int k) {
    const float t[6] = {0.23955940f, 0.20009682f, 0.11660614f,
                        0.04740849f, 0.01344761f, 0.00266126f};
    return t[k];
}

static __device__ __forceinline__ u64 pk(float lo, float hi) {
    u64 r; asm("mov.b64 %0, {%1, %2};" : "=l"(r) : "f"(lo), "f"(hi)); return r;
}
static __device__ __forceinline__ void upk(u64 v, float& lo, float& hi) {
    asm("mov.b64 {%0, %1}, %2;" : "=f"(lo), "=f"(hi) : "l"(v));
}
static __device__ __forceinline__ u64 f2mul(u64 a, u64 b) {
    u64 d; asm("mul.rn.f32x2 %0, %1, %2;" : "=l"(d) : "l"(a), "l"(b)); return d;
}
static __device__ __forceinline__ u64 f2fma(u64 a, u64 b, u64 c) {
    u64 d; asm("fma.rn.f32x2 %0, %1, %2, %3;" : "=l"(d) : "l"(a), "l"(b), "l"(c)); return d;
}
static __device__ __forceinline__ u64 f2add(u64 a, u64 b) {
    u64 d; asm("add.rn.f32x2 %0, %1, %2;" : "=l"(d) : "l"(a), "l"(b)); return d;
}

// One step of the fused blur/argmax pipeline.
//  U      : static slot phase (i mod 11)
//  GUARD  : head/tail mode — runtime row/load bounds checks (warp-uniform)
//  EMIT   : emit completed output row (slot U) into the running argmax
// cur holds row r; this step consumes it, loads row r+1 into cur.
template<int U, bool GUARD, bool EMIT>
static __device__ __forceinline__ void step(
    const float* __restrict__ rp,   // block load base: row of U=0 load (main)
    const float* __restrict__ ip,   // image base (GUARD mode addressing)
    int r, int col0,
    float (&cur)[6], u64 (&acc)[11][3], const u64 (&w2)[6],
    bool l0, bool l31, float& bestv, int& bestlin, int ebl)
{
    // ---- load row r+1 ----
    float nc[6];
    bool loadok = true, rowok = true;
    if (GUARD) {
        loadok = ((unsigned)(r + 1) < (unsigned)IH);
        rowok  = ((unsigned)r       < (unsigned)IH);
    }
    if (loadok) {
        const float* p = GUARD ? (ip + (r + 1) * IW + col0) : (rp + U * IW);
        float2 a = *(const float2*)p;
        float2 b = *(const float2*)(p + 2);
        float2 c = *(const float2*)(p + 4);
        nc[0] = a.x; nc[1] = a.y; nc[2] = b.x;
        nc[3] = b.y; nc[4] = c.x; nc[5] = c.y;
    } else {
        nc[0] = nc[1] = nc[2] = nc[3] = nc[4] = nc[5] = 0.f;
    }

    if (rowok) {
        // halos: lo = cols col0-5..col0-1, hi = cols col0+6..col0+10
        float hl[5], hh[5];
        hl[0] = __shfl_up_sync(FULLMASK, cur[1], 1);
        hl[1] = __shfl_up_sync(FULLMASK, cur[2], 1);
        hl[2] = __shfl_up_sync(FULLMASK, cur[3], 1);
        hl[3] = __shfl_up_sync(FULLMASK, cur[4], 1);
        hl[4] = __shfl_up_sync(FULLMASK, cur[5], 1);
        hh[0] = __shfl_down_sync(FULLMASK, cur[0], 1);
        hh[1] = __shfl_down_sync(FULLMASK, cur[1], 1);
        hh[2] = __shfl_down_sync(FULLMASK, cur[2], 1);
        hh[3] = __shfl_down_sync(FULLMASK, cur[3], 1);
        hh[4] = __shfl_down_sync(FULLMASK, cur[4], 1);
        if (l0)  { hl[0]=0.f; hl[1]=0.f; hl[2]=0.f; hl[3]=0.f; hl[4]=0.f; }
        if (l31) { hh[0]=0.f; hh[1]=0.f; hh[2]=0.f; hh[3]=0.f; hh[4]=0.f; }

        // adjacent pairs over extended segment e[0..15]
        u64 P[15];
        P[0]  = pk(hl[0], hl[1]);
        P[1]  = pk(hl[1], hl[2]);
        P[2]  = pk(hl[2], hl[3]);
        P[3]  = pk(hl[3], hl[4]);
        P[4]  = pk(hl[4], cur[0]);
        P[5]  = pk(cur[0], cur[1]);
        P[6]  = pk(cur[1], cur[2]);
        P[7]  = pk(cur[2], cur[3]);
        P[8]  = pk(cur[3], cur[4]);
        P[9]  = pk(cur[4], cur[5]);
        P[10] = pk(cur[5], hh[0]);
        P[11] = pk(hh[0], hh[1]);
        P[12] = pk(hh[1], hh[2]);
        P[13] = pk(hh[2], hh[3]);
        P[14] = pk(hh[3], hh[4]);

        // horizontal blur (packed, even/odd split chains)
        u64 h2[3];
#pragma unroll
        for (int j = 0; j < 3; ++j) {
            u64 sa = f2mul(P[2*j + 0], w2[5]);
            sa = f2fma(P[2*j + 2],  w2[3], sa);
            sa = f2fma(P[2*j + 4],  w2[1], sa);
            sa = f2fma(P[2*j + 6],  w2[1], sa);
            sa = f2fma(P[2*j + 8],  w2[3], sa);
            sa = f2fma(P[2*j + 10], w2[5], sa);
            u64 sb = f2mul(P[2*j + 1], w2[4]);
            sb = f2fma(P[2*j + 3],  w2[2], sb);
            sb = f2fma(P[2*j + 5],  w2[0], sb);
            sb = f2fma(P[2*j + 7],  w2[2], sb);
            sb = f2fma(P[2*j + 9],  w2[4], sb);
            h2[j] = f2add(sa, sb);
        }

        // vertical taps: k=0..9 accumulate, k=10 overwrites recycled slot
#pragma unroll
        for (int k = 0; k < 10; ++k) {
            const u64 wv = w2[k <= 5 ? 5 - k : k - 5];
            const int s = (U + k) % 11;
            acc[s][0] = f2fma(h2[0], wv, acc[s][0]);
            acc[s][1] = f2fma(h2[1], wv, acc[s][1]);
            acc[s][2] = f2fma(h2[2], wv, acc[s][2]);
        }
        {
            const int s = (U + 10) % 11;
            acc[s][0] = f2mul(h2[0], w2[5]);
            acc[s][1] = f2mul(h2[1], w2[5]);
            acc[s][2] = f2mul(h2[2], w2[5]);
        }
    } else {
        const int s = (U + 10) % 11;
        acc[s][0] = 0ull; acc[s][1] = 0ull; acc[s][2] = 0ull;
    }

    if (EMIT) {
        float a0, a1, a2, a3, a4, a5;
        upk(acc[U][0], a0, a1);
        upk(acc[U][1], a2, a3);
        upk(acc[U][2], a4, a5);
        const float m01 = fmaxf(a0, a1);
        const float m23 = fmaxf(a2, a3);
        const float m45 = fmaxf(a4, a5);
        const float rowmax = fmaxf(fmaxf(m01, m23), m45);
        if (rowmax > bestv) {           // rare
            bestv = rowmax;
            int c = 5;
            if (a4 == rowmax) c = 4;
            if (a3 == rowmax) c = 3;
            if (a2 == rowmax) c = 2;
            if (a1 == rowmax) c = 1;
            if (a0 == rowmax) c = 0;
            bestlin = ebl + U * IW + c;
        }
    }

#pragma unroll
    for (int c = 0; c < 6; ++c) cur[c] = nc[c];
}

// One CTA (64 threads = 2 warps) per (b,k) image; warp w owns output rows
// [w*128, w*128+128), lane owns 6 columns. Head (11 guarded iters) + main
// (11x11 branch-free iters) + tail (6 guarded iters).
__global__ __launch_bounds__(64, 8)
void dark_decode_kernel(const float* __restrict__ hm,
                        float* __restrict__ out, int n_img)
{
    const int img  = blockIdx.x;
    const int warp = threadIdx.x >> 5;
    const int lane = threadIdx.x & 31;
    const float* __restrict__ ip = hm + (long long)img * (IH * IW);
    const int base = warp * 128;
    const int col0 = lane * 6;
    const bool l0  = (lane == 0);
    const bool l31 = (lane == 31);

    u64 w2[6];
#pragma unroll
    for (int k = 0; k < 6; ++k) w2[k] = pk(wt(k), wt(k));

    u64 acc[11][3];   // no init needed: every slot is overwritten before emit

    float cur[6];
    {   // row base-5 (warp0: OOB -> zeros)
        const int r0 = base - 5;
        if (r0 >= 0) {
            const float* p = ip + r0 * IW + col0;
            float2 a = *(const float2*)p;
            float2 b = *(const float2*)(p + 2);
            float2 c = *(const float2*)(p + 4);
            cur[0]=a.x; cur[1]=a.y; cur[2]=b.x; cur[3]=b.y; cur[4]=c.x; cur[5]=c.y;
        } else {
#pragma unroll
            for (int c = 0; c < 6; ++c) cur[c] = 0.f;
        }
    }

    float bestv   = -3.4e38f;
    int   bestlin = 0;

    // ---- head: i = 0..10 (r = base-5+i), guarded; emit only at i=10 ----
    {
        const int eblh = (base - 10) * IW + col0;
#define HSTEP(U, EM) step<U, true, EM>(ip, ip, base - 5 + (U), col0, cur, acc, \
                                        w2, l0, l31, bestv, bestlin, eblh)
        HSTEP(0, false); HSTEP(1, false); HSTEP(2, false); HSTEP(3, false);
        HSTEP(4, false); HSTEP(5, false); HSTEP(6, false); HSTEP(7, false);
        HSTEP(8, false); HSTEP(9, false); HSTEP(10, true);
#undef HSTEP
    }

    // ---- main: i = 11..131, 11 blocks x 11 steps, branch-free ----
    {
        const float* rp = ip + (base + 7) * IW + col0;   // row r+1 at ib=1,U=0
        int ebl = (base + 1) * IW + col0;                // ro at ib=1,U=0
#define MSTEP(U) step<U, false, true>(rp, ip, 0, col0, cur, acc, w2, l0, l31, \
                                      bestv, bestlin, ebl)
        for (int ib = 0; ib < 11; ++ib) {
            MSTEP(0); MSTEP(1); MSTEP(2); MSTEP(3); MSTEP(4); MSTEP(5);
            MSTEP(6); MSTEP(7); MSTEP(8); MSTEP(9); MSTEP(10);
            rp  += 11 * IW;
            ebl += 11 * IW;
        }
#undef MSTEP
    }

    // ---- tail: i = 132..137 (u = 0..5), guarded, always emit ----
    {
        const int eblt = (base + 122) * IW + col0;
#define TSTEP(U) step<U, true, true>(ip, ip, base + 127 + (U), col0, cur, acc, \
                                     w2, l0, l31, bestv, bestlin, eblt)
        TSTEP(0); TSTEP(1); TSTEP(2); TSTEP(3); TSTEP(4); TSTEP(5);
#undef TSTEP
    }

    // intra-warp argmax reduce (larger value wins; tie -> smaller linear index)
#pragma unroll
    for (int off = 16; off >= 1; off >>= 1) {
        const float ov = __shfl_xor_sync(FULLMASK, bestv, off);
        const int   oi = __shfl_xor_sync(FULLMASK, bestlin, off);
        if (ov > bestv || (ov == bestv && oi < bestlin)) { bestv = ov; bestlin = oi; }
    }

    __shared__ float s_v[2];
    __shared__ int   s_i[2];
    if (lane == 0) { s_v[warp] = bestv; s_i[warp] = bestlin; }
    __syncthreads();
    if (warp != 0) return;

    float fv; int fl;
    {
        const float v0 = s_v[0], v1 = s_v[1];
        const int   i0 = s_i[0], i1 = s_i[1];
        if (v1 > v0 || (v1 == v0 && i1 < i0)) { fv = v1; fl = i1; }
        else                                  { fv = v0; fl = i0; }
    }
    const int py = fl / IW;
    const int px = fl - py * IW;

    float offx = 0.f, offy = 0.f;
    const bool bok = (px >= 1) && (px < IW - 1) && (py >= 1) && (py < IH - 1);
    if (bok) {
        // 39 hblur values: flat j in [0,39), rr = py-6 + j/3, cc = px-1 + j%3
        float h0 = 0.f, h1 = 0.f;
        {
            int j = lane;
            int rr = py - 6 + j / 3;
            int cc = px - 1 + (j - (j / 3) * 3);
            if (rr >= 0 && rr < IH) {
                const float* rp2 = ip + rr * IW;
                float s = 0.f;
#pragma unroll
                for (int d = -5; d <= 5; ++d) {
                    const int c = cc + d;
                    float v = 0.f;
                    if ((unsigned)c < (unsigned)IW) v = rp2[c];
                    s += v * wt(d < 0 ? -d : d);
                }
                h0 = s;
            }
            j = lane + 32;
            if (j < 39) {
                rr = py - 6 + j / 3;
                cc = px - 1 + (j - (j / 3) * 3);
                if (rr >= 0 && rr < IH) {
                    const float* rp2 = ip + rr * IW;
                    float s = 0.f;
#pragma unroll
                    for (int d = -5; d <= 5; ++d) {
                        const int c = cc + d;
                        float v = 0.f;
                        if ((unsigned)c < (unsigned)IW) v = rp2[c];
                        s += v * wt(d < 0 ? -d : d);
                    }
                    h1 = s;
                }
            }
        }
        // lanes 0..8: vertical blur -> patch entry p(a,b), a=lane/3, b=lane%3
        const int a = lane / 3;
        const int b = lane - a * 3;
        float p = 0.f;
#pragma unroll
        for (int t = 0; t < 11; ++t) {
            const int j = (a + t) * 3 + b;
            const float va = __shfl_sync(FULLMASK, h0, j & 31);
            const float vb = __shfl_sync(FULLMASK, h1, j & 31);
            const float hv = (j < 32) ? va : vb;
            p += hv * wt(t <= 5 ? 5 - t : t - 5);
        }
        const float p00 = __shfl_sync(FULLMASK, p, 0);
        const float p01 = __shfl_sync(FULLMASK, p, 1);
        const float p02 = __shfl_sync(FULLMASK, p, 2);
        const float p10 = __shfl_sync(FULLMASK, p, 3);
        const float p11 = __shfl_sync(FULLMASK, p, 4);
        const float p12 = __shfl_sync(FULLMASK, p, 5);
        const float p20 = __shfl_sync(FULLMASK, p, 6);
        const float p21 = __shfl_sync(FULLMASK, p, 7);
        const float p22 = __shfl_sync(FULLMASK, p, 8);

        const float dx  = (p12 - p10) * 0.5f;
        const float dy  = (p21 - p01) * 0.5f;
        const float dxx = p12 - 2.f * p11 + p10;
        const float dyy = p21 - 2.f * p11 + p01;
        const float dxy = (p22 - p20 - p02 + p00) * 0.25f;
        const float det = dxx * dyy - dxy * dxy;
        if (fabsf(det) >= 1e-6f && dxx < 0.f) {
            const float ox = -(dyy * dx - dxy * dy) / det;
            const float oy = -(dxx * dy - dxy * dx) / det;
            offx = fminf(fmaxf(ox, -0.5f), 0.5f);
            offy = fminf(fmaxf(oy, -0.5f), 0.5f);
        }
    }

    if (lane == 0) {
        const float xo = fminf(fmaxf((float)px + offx, 0.f), (float)(IW - 1));
        const float yo = fminf(fmaxf((float)py + offy, 0.f), (float)(IH - 1));
        out[2 * img + 0] = xo;                       // coords[...,0] = x
        out[2 * img + 1] = yo;                       // coords[...,1] = y
        out[(long long)2 * n_img + img] = fv;        // max_vals
    }
}

extern "C" void kernel_launch(void* const* d_in, const int* in_sizes, int n_in,
                              void* d_out, int out_size)
{
    const float* hm = (const float*)d_in[0];
    // d_in[1] is kernel_size (always 11 in this problem; taps are baked in)
    const int n_img = in_sizes[0] / (IH * IW);
    dark_decode_kernel<<<n_img, 64>>>(hm, (float*)d_out, n_img);
}